// round 8
// baseline (speedup 1.0000x reference)
#include <cuda_runtime.h>
#include <cuda_fp16.h>
#include <cstdint>

#define Nq 400000
#define Kq 27
#define Cq 64
#define Dq 128
#define Hq 128
#define Wq 128
#define EPSq 1e-5f
#define TABLE_SIZE (2 * Dq * Hq * Wq)   // 4,194,304
#define TILE 256
#define NTILES ((Nq + TILE - 1) / TILE)  // 1563
#define ENT_CAP 1024                     // non-center entries per tile (mean ~634, max ~830)

// ---- scratch (device globals; allocation-free rule) ----
__device__ int   g_table[TABLE_SIZE];
__device__ int   g_nbr[Kq * Nq];              // for layer1
__device__ int2  g_ent[(size_t)NTILES * ENT_CAP]; // (input voxel, output local)
__device__ int   g_goff[NTILES * 28];         // per-tile CSR over k (local offsets)
__device__ __half g_a1[(size_t)Nq * Cq];
__device__ __half g_a2[(size_t)Nq * Cq];
__device__ uint2 g_wf2[Kq * 1024];            // B fragments fp16
__device__ uint2 g_wf3[Kq * 1024];

// ---------------------------------------------------------------------------
// helpers
// ---------------------------------------------------------------------------
__device__ __forceinline__ uint32_t smem_u32(const void* p) {
    uint32_t a;
    asm("{ .reg .u64 t; cvta.to.shared.u64 t, %1; cvt.u32.u64 %0, t; }" : "=r"(a) : "l"(p));
    return a;
}
__device__ __forceinline__ void mma_f16(float* d, const uint32_t* a, uint32_t b0, uint32_t b1) {
    asm volatile(
        "mma.sync.aligned.m16n8k16.row.col.f32.f16.f16.f32 "
        "{%0,%1,%2,%3}, {%4,%5,%6,%7}, {%8,%9}, {%0,%1,%2,%3};"
        : "+f"(d[0]), "+f"(d[1]), "+f"(d[2]), "+f"(d[3])
        : "r"(a[0]), "r"(a[1]), "r"(a[2]), "r"(a[3]), "r"(b0), "r"(b1));
}
__device__ __forceinline__ void ldm_x4(uint32_t* a, uint32_t addr) {
    asm volatile(
        "ldmatrix.sync.aligned.m8n8.x4.shared.b16 {%0,%1,%2,%3}, [%4];"
        : "=r"(a[0]), "=r"(a[1]), "=r"(a[2]), "=r"(a[3]) : "r"(addr));
}
__device__ __forceinline__ void cp16(uint32_t dst, const void* src, uint32_t srcsize) {
    asm volatile("cp.async.cg.shared.global [%0], [%1], 16, %2;"
                 :: "r"(dst), "l"(src), "r"(srcsize) : "memory");
}
__device__ __forceinline__ void cp_commit() {
    asm volatile("cp.async.commit_group;" ::: "memory");
}
__device__ __forceinline__ void cp_wait0() {
    asm volatile("cp.async.wait_group 0;" ::: "memory");
}

// ---------------------------------------------------------------------------
// rulebook
// ---------------------------------------------------------------------------
__global__ void init_table_kernel() {
    int i = blockIdx.x * blockDim.x + threadIdx.x;
    ((int4*)g_table)[i] = make_int4(-1, -1, -1, -1);
}

__global__ void scatter_kernel(const int* __restrict__ coords) {
    int i = blockIdx.x * blockDim.x + threadIdx.x;
    if (i >= Nq) return;
    int b = coords[i * 4 + 0], z = coords[i * 4 + 1];
    int y = coords[i * 4 + 2], x = coords[i * 4 + 3];
    g_table[((b * Dq + z) * Hq + y) * Wq + x] = i;
}

// per-tile: neighbor lookups, per-k CSR over non-center taps, entry fill
__global__ void __launch_bounds__(256) build_rules_kernel(const int* __restrict__ coords) {
    __shared__ int s_cnt[Kq];
    __shared__ int s_cur[Kq];
    __shared__ int s_off[Kq + 1];
    const int tid  = threadIdx.x;
    const int tile = blockIdx.x;
    const int v    = tile * TILE + tid;
    const bool act = (v < Nq);

    if (tid < Kq) s_cnt[tid] = 0;
    __syncthreads();

    int rn[Kq];
    if (act) {
        int4 cc = __ldg((const int4*)(coords + v * 4));
        int b = cc.x, z = cc.y, y = cc.z, x = cc.w;
        #pragma unroll
        for (int k = 0; k < Kq; k++) {
            int dz = k / 9 - 1, dy = (k / 3) % 3 - 1, dx = k % 3 - 1;
            int nz = z + dz, ny = y + dy, nx = x + dx;
            int r = -1;
            if (nz >= 0 && nz < Dq && ny >= 0 && ny < Hq && nx >= 0 && nx < Wq)
                r = g_table[((b * Dq + nz) * Hq + ny) * Wq + nx];
            rn[k] = r;
            g_nbr[k * Nq + v] = r;
            if (k != 13 && r >= 0) atomicAdd(&s_cnt[k], 1);
        }
    }
    __syncthreads();
    if (tid == 0) {
        int run = 0;
        #pragma unroll
        for (int k = 0; k < Kq; k++) { s_off[k] = run; run += s_cnt[k]; }
        s_off[Kq] = run;
    }
    __syncthreads();
    if (tid < Kq) s_cur[tid] = s_off[tid];
    if (tid < Kq + 1) g_goff[tile * 28 + tid] = s_off[tid];
    __syncthreads();
    if (act) {
        #pragma unroll
        for (int k = 0; k < Kq; k++) {
            if (k != 13 && rn[k] >= 0) {
                int pos = atomicAdd(&s_cur[k], 1);
                if (pos < ENT_CAP)
                    g_ent[(size_t)tile * ENT_CAP + pos] = make_int2(rn[k], tid);
            }
        }
    }
}

// ---------------------------------------------------------------------------
// weight prep: w[k][cin][cout] fp32 -> mma B fragments, single fp16
// ---------------------------------------------------------------------------
__global__ void prep_w_kernel(const float* __restrict__ w, uint2* __restrict__ frag) {
    int idx = blockIdx.x * blockDim.x + threadIdx.x;
    if (idx >= Kq * 1024) return;
    int lane = idx & 31;
    int n8   = (idx >> 5) & 7;
    int kc   = (idx >> 8) & 3;
    int k    = idx >> 10;
    int n  = n8 * 8 + (lane >> 2);
    int c0 = kc * 16 + (lane & 3) * 2;
    uint32_t r[2];
    #pragma unroll
    for (int h = 0; h < 2; h++) {
        uint32_t packed = 0;
        #pragma unroll
        for (int e = 0; e < 2; e++) {
            float x = w[(k * 64 + (c0 + h * 8 + e)) * 64 + n];
            __half hv = __float2half_rn(x);
            uint16_t bits = *(uint16_t*)&hv;
            packed |= (uint32_t)bits << (16 * e);
        }
        r[h] = packed;
    }
    frag[idx] = make_uint2(r[0], r[1]);
}

// ---------------------------------------------------------------------------
// layer 1 (cin=1): direct sparse FMA; 2 threads per voxel
// ---------------------------------------------------------------------------
__global__ void __launch_bounds__(256) layer1_kernel(
    const float* __restrict__ feats, const float* __restrict__ w,
    const float* __restrict__ bias,
    const float* __restrict__ gg, const float* __restrict__ be,
    const float* __restrict__ mm, const float* __restrict__ vv,
    __half* __restrict__ oa)
{
    __shared__ float s_w[Kq * Cq];
    __shared__ float s_scale[Cq], s_shift[Cq];
    const int tid = threadIdx.x;
    if (tid < Cq) {
        float sc = gg[tid] * rsqrtf(vv[tid] + EPSq);
        s_scale[tid] = sc;
        s_shift[tid] = (bias[tid] - mm[tid]) * sc + be[tid];
    }
    for (int t = tid; t < Kq * Cq; t += 256) s_w[t] = w[t];
    __syncthreads();

    int idx = blockIdx.x * blockDim.x + tid;
    int v = idx >> 1;
    if (v >= Nq) return;
    int c0 = (idx & 1) * 32;

    float acc[32];
    #pragma unroll
    for (int c = 0; c < 32; c++) acc[c] = 0.f;

    #pragma unroll
    for (int k = 0; k < Kq; k++) {
        int n = g_nbr[k * Nq + v];
        if (n >= 0) {
            float f = __ldg(&feats[n]);
            const float* wr = &s_w[k * Cq + c0];
            #pragma unroll
            for (int c = 0; c < 32; c++) acc[c] = fmaf(f, wr[c], acc[c]);
        }
    }
    __half2 outp[16];
    #pragma unroll
    for (int c = 0; c < 32; c += 2) {
        float o0 = fmaxf(fmaf(acc[c],     s_scale[c0 + c],     s_shift[c0 + c]),     0.f);
        float o1 = fmaxf(fmaf(acc[c + 1], s_scale[c0 + c + 1], s_shift[c0 + c + 1]), 0.f);
        outp[c >> 1] = __floats2half2_rn(o0, o1);
    }
    uint4* dst = (uint4*)(oa + (size_t)v * Cq + c0);
    const uint4* srcp = (const uint4*)outp;
    dst[0] = srcp[0]; dst[1] = srcp[1]; dst[2] = srcp[2]; dst[3] = srcp[3];
}

// ---------------------------------------------------------------------------
// conv64 fused: per output tile (256 voxels), fp32 smem accumulators.
// For each k: gather rows -> MMA (warp = exclusive 8-ch slice) -> scatter-add
// fragments into acc by output-local index. Center tap (k=13) dense/identity.
// ---------------------------------------------------------------------------
#define ACC_STRIDE 66                       // floats per acc row (bank stagger)
#define SM_ACC  0                           // 256*66*4 = 67584
#define SM_Af   67584                       // 256*128  = 32768
#define SM_Bf   100352                      // 8192
#define SM_OL   108544                      // 256*4 = 1024
#define SM_GOFF 109568                      // 28*4 = 112 -> pad 128
#define SM_SCL  109696                      // 256
#define SM_SFT  109952                      // 256
#define SM_TOT  110208

__global__ void __launch_bounds__(256, 2) conv_tile_kernel(
    const __half* __restrict__ xa,
    const uint2* __restrict__ wfrag,
    const float* __restrict__ bias,
    const float* __restrict__ gg, const float* __restrict__ be,
    const float* __restrict__ mm, const float* __restrict__ vv,
    float* __restrict__ out_f32, __half* __restrict__ oa, int outmode)
{
    extern __shared__ char smc[];
    float* s_acc   = (float*)(smc + SM_ACC);
    int*   s_ol    = (int*)(smc + SM_OL);
    int*   s_goff  = (int*)(smc + SM_GOFF);
    float* s_scale = (float*)(smc + SM_SCL);
    float* s_shift = (float*)(smc + SM_SFT);
    const uint32_t sa_base = smem_u32(smc) + SM_Af;
    const uint32_t sb_base = smem_u32(smc) + SM_Bf;

    const int tid  = threadIdx.x;
    const int lane = tid & 31;
    const int warp = tid >> 5;              // = n8 channel slice
    const int tile = blockIdx.x;
    const int nvox = min(TILE, Nq - tile * TILE);

    if (tid < 28) s_goff[tid] = g_goff[tile * 28 + tid];
    if (tid < Cq) {
        float sc = gg[tid] * rsqrtf(vv[tid] + EPSq);
        s_scale[tid] = sc;
        s_shift[tid] = (bias[tid] - mm[tid]) * sc + be[tid];
    }
    // zero accumulators
    float2* accz = (float2*)s_acc;
    #pragma unroll
    for (int i = 0; i < (TILE * ACC_STRIDE) / 2 / 256; i++)
        accz[tid + i * 256] = make_float2(0.f, 0.f);
    for (int i = (TILE * ACC_STRIDE) / 2 / 256 * 256 + tid;
         i < (TILE * ACC_STRIDE) / 2; i += 256)
        accz[i] = make_float2(0.f, 0.f);
    __syncthreads();

    const int rowl = (lane & 7) | (lane & 8);
    const uint32_t colh = (lane & 16);
    const int qrow = lane >> 2;
    const int c_base = warp * 8 + (lane & 3) * 2;

    for (int k = 0; k < Kq; k++) {
        int rows;
        if (k == 13) {
            rows = nvox;
            // dense contiguous gather: thread -> row tid
            if (tid < nvox) {
                const __half* src = xa + (size_t)(tile * TILE + tid) * Cq;
                uint32_t dbase = sa_base + tid * 128;
                uint32_t swz = (tid & 7) << 4;
                #pragma unroll
                for (int j = 0; j < 8; j++)
                    cp16(dbase + (((uint32_t)(j << 4)) ^ swz), src + j * 8, 16u);
                s_ol[tid] = tid;
            }
        } else {
            int gs = s_goff[k], ge = s_goff[k + 1];
            rows = ge - gs;
            for (int r = tid; r < rows; r += 256) {
                int2 e = __ldg(&g_ent[(size_t)tile * ENT_CAP + gs + r]);
                const __half* src = xa + (size_t)e.x * Cq;
                uint32_t dbase = sa_base + r * 128;
                uint32_t swz = (r & 7) << 4;
                #pragma unroll
                for (int j = 0; j < 8; j++)
                    cp16(dbase + (((uint32_t)(j << 4)) ^ swz), src + j * 8, 16u);
                s_ol[r] = e.y;
            }
        }
        // stage B fragments for this k: 8KB, 32B/thread
        {
            const char* wsrc = (const char*)(wfrag + k * 1024) + tid * 32;
            uint32_t wdst = sb_base + tid * 32;
            cp16(wdst,      wsrc,      16u);
            cp16(wdst + 16, wsrc + 16, 16u);
        }
        cp_commit();
        cp_wait0();
        __syncthreads();

        const uint2* sb = (const uint2*)(smc + SM_Bf);
        const int mtiles = (rows + 15) >> 4;
        for (int mt = 0; mt < mtiles; mt++) {
            const int row = mt * 16 + rowl;
            const uint32_t swz = (row & 7) << 4;
            float d[4] = {0.f, 0.f, 0.f, 0.f};
            #pragma unroll
            for (int kc = 0; kc < 4; kc++) {
                uint32_t a[4];
                ldm_x4(a, sa_base + row * 128 + (((uint32_t)((kc << 5) | colh)) ^ swz));
                uint2 bh = sb[(kc * 8 + warp) * 32 + lane];
                mma_f16(d, a, bh.x, bh.y);
            }
            // scatter-add into fp32 accumulators (exclusive (ol, c) per thread)
            int r0 = mt * 16 + qrow;
            int r1 = r0 + 8;
            if (r0 < rows) {
                float2* p = (float2*)&s_acc[s_ol[r0] * ACC_STRIDE + c_base];
                float2 v0 = *p; v0.x += d[0]; v0.y += d[1]; *p = v0;
            }
            if (r1 < rows) {
                float2* p = (float2*)&s_acc[s_ol[r1] * ACC_STRIDE + c_base];
                float2 v1 = *p; v1.x += d[2]; v1.y += d[3]; *p = v1;
            }
        }
        __syncthreads();
    }

    // epilogue: BN + ReLU
    if (tid < nvox) {
        const float* arow = &s_acc[tid * ACC_STRIDE];
        if (outmode == 0) {
            float* orow = out_f32 + (size_t)(tile * TILE + tid) * Cq;
            #pragma unroll
            for (int j = 0; j < 32; j++) {
                int c = j * 2;
                float2 a = *(const float2*)&arow[c];
                float o0 = fmaxf(fmaf(a.x, s_scale[c],     s_shift[c]),     0.f);
                float o1 = fmaxf(fmaf(a.y, s_scale[c + 1], s_shift[c + 1]), 0.f);
                *(float2*)(orow + c) = make_float2(o0, o1);
            }
        } else {
            __half* orow = oa + (size_t)(tile * TILE + tid) * Cq;
            #pragma unroll
            for (int j = 0; j < 32; j++) {
                int c = j * 2;
                float2 a = *(const float2*)&arow[c];
                float o0 = fmaxf(fmaf(a.x, s_scale[c],     s_shift[c]),     0.f);
                float o1 = fmaxf(fmaf(a.y, s_scale[c + 1], s_shift[c + 1]), 0.f);
                *(__half2*)(orow + c) = __floats2half2_rn(o0, o1);
            }
        }
    }
}

// ---------------------------------------------------------------------------
extern "C" void kernel_launch(void* const* d_in, const int* in_sizes, int n_in,
                              void* d_out, int out_size)
{
    const float* feats  = (const float*)d_in[0];
    const int*   coords = (const int*)  d_in[1];
    const float* w1 = (const float*)d_in[2];
    const float* b1 = (const float*)d_in[3];
    const float* g1 = (const float*)d_in[4];
    const float* be1= (const float*)d_in[5];
    const float* m1 = (const float*)d_in[6];
    const float* v1 = (const float*)d_in[7];
    const float* w2 = (const float*)d_in[8];
    const float* b2 = (const float*)d_in[9];
    const float* g2 = (const float*)d_in[10];
    const float* be2= (const float*)d_in[11];
    const float* m2 = (const float*)d_in[12];
    const float* v2 = (const float*)d_in[13];
    const float* w3 = (const float*)d_in[14];
    const float* b3 = (const float*)d_in[15];
    const float* g3 = (const float*)d_in[16];
    const float* be3= (const float*)d_in[17];
    const float* m3 = (const float*)d_in[18];
    const float* v3 = (const float*)d_in[19];
    float* out = (float*)d_out;

    cudaFuncSetAttribute(conv_tile_kernel,
                         cudaFuncAttributeMaxDynamicSharedMemorySize, SM_TOT);

    uint2 *wf2, *wf3;
    cudaGetSymbolAddress((void**)&wf2, g_wf2);
    cudaGetSymbolAddress((void**)&wf3, g_wf3);
    __half *a1, *a2;
    cudaGetSymbolAddress((void**)&a1, g_a1);
    cudaGetSymbolAddress((void**)&a2, g_a2);

    // rulebook
    init_table_kernel<<<4096, 256>>>();
    scatter_kernel<<<(Nq + 255) / 256, 256>>>(coords);
    prep_w_kernel<<<(Kq * 1024 + 255) / 256, 256>>>(w2, wf2);
    prep_w_kernel<<<(Kq * 1024 + 255) / 256, 256>>>(w3, wf3);
    build_rules_kernel<<<NTILES, 256>>>(coords);

    // layer 1
    layer1_kernel<<<(Nq * 2 + 255) / 256, 256>>>(feats, w1, b1, g1, be1, m1, v1, a1);
    // layer 2
    conv_tile_kernel<<<NTILES, 256, SM_TOT>>>(a1, wf2, b2, g2, be2, m2, v2,
                                              nullptr, a2, 1);
    // layer 3
    conv_tile_kernel<<<NTILES, 256, SM_TOT>>>(a2, wf3, b3, g3, be3, m3, v3,
                                              out, nullptr, 0);
}

// round 9
// speedup vs baseline: 1.5402x; 1.5402x over previous
#include <cuda_runtime.h>
#include <cuda_fp16.h>
#include <cstdint>

#define Nq 400000
#define Kq 27
#define Cq 64
#define Dq 128
#define Hq 128
#define Wq 128
#define EPSq 1e-5f
#define TABLE_SIZE (2 * Dq * Hq * Wq)   // 4,194,304
#define SEGK 49152                       // per-offset staging capacity (k != 13)
#define KB13 (13 * SEGK)                 // center segment base; size Nq exactly
#define CAPq (KB13 + Nq + 13 * SEGK)     // 1,677,952 pair rows
#define MAXCHUNK 16384
#define PA_GRID 592

// ---- scratch (device globals; allocation-free rule) ----
__device__ int   g_table[TABLE_SIZE];
__device__ int   g_nbr[Kq * Nq];          // rulebook, k-major (layer1 + fill)
__device__ int   g_kpos[32];              // per-offset fill cursors
__device__ int   g_kend[32];              // segment end (base + count)
__device__ int   g_nT;                    // total 128-row chunks
__device__ int   g_chunk_k[MAXCHUNK];
__device__ int   g_chunk_s[MAXCHUNK];     // start pair index of chunk
__device__ int   g_pin[CAPq];             // pair -> input voxel
__device__ int   g_plist[(size_t)Nq * Kq];// voxel-major pair ids
__device__ int   g_deg[Nq];
__device__ __half g_stg[(size_t)CAPq * Cq];  // staged conv partials (fp16)
__device__ __half g_a1[(size_t)Nq * Cq];
__device__ __half g_a2[(size_t)Nq * Cq];
__device__ uint2 g_wf2[Kq * 1024];        // B fragments fp16
__device__ uint2 g_wf3[Kq * 1024];

__host__ __device__ __forceinline__ int kbase(int k) {
    return (k <= 13) ? k * SEGK : KB13 + Nq + (k - 14) * SEGK;
}

// ---------------------------------------------------------------------------
// helpers
// ---------------------------------------------------------------------------
__device__ __forceinline__ uint32_t smem_u32(const void* p) {
    uint32_t a;
    asm("{ .reg .u64 t; cvta.to.shared.u64 t, %1; cvt.u32.u64 %0, t; }" : "=r"(a) : "l"(p));
    return a;
}
__device__ __forceinline__ void mma_f16(float* d, const uint32_t* a, uint32_t b0, uint32_t b1) {
    asm volatile(
        "mma.sync.aligned.m16n8k16.row.col.f32.f16.f16.f32 "
        "{%0,%1,%2,%3}, {%4,%5,%6,%7}, {%8,%9}, {%0,%1,%2,%3};"
        : "+f"(d[0]), "+f"(d[1]), "+f"(d[2]), "+f"(d[3])
        : "r"(a[0]), "r"(a[1]), "r"(a[2]), "r"(a[3]), "r"(b0), "r"(b1));
}
__device__ __forceinline__ void ldm_x4(uint32_t* a, uint32_t addr) {
    asm volatile(
        "ldmatrix.sync.aligned.m8n8.x4.shared.b16 {%0,%1,%2,%3}, [%4];"
        : "=r"(a[0]), "=r"(a[1]), "=r"(a[2]), "=r"(a[3]) : "r"(addr));
}
__device__ __forceinline__ void cp16(uint32_t dst, const void* src, uint32_t srcsize) {
    asm volatile("cp.async.cg.shared.global [%0], [%1], 16, %2;"
                 :: "r"(dst), "l"(src), "r"(srcsize) : "memory");
}
__device__ __forceinline__ void cp_commit() {
    asm volatile("cp.async.commit_group;" ::: "memory");
}

// ---------------------------------------------------------------------------
// rulebook
// ---------------------------------------------------------------------------
__global__ void init_table_kernel() {
    int i = blockIdx.x * blockDim.x + threadIdx.x;
    ((int4*)g_table)[i] = make_int4(-1, -1, -1, -1);
    if (blockIdx.x == 0 && threadIdx.x < Kq) g_kpos[threadIdx.x] = kbase(threadIdx.x);
}

__global__ void scatter_kernel(const int* __restrict__ coords) {
    int i = blockIdx.x * blockDim.x + threadIdx.x;
    if (i >= Nq) return;
    int b = coords[i * 4 + 0], z = coords[i * 4 + 1];
    int y = coords[i * 4 + 2], x = coords[i * 4 + 3];
    g_table[((b * Dq + z) * Hq + y) * Wq + x] = i;
}

// one pass: neighbor lookups + g_nbr + pair fill (fixed per-k segments)
__global__ void __launch_bounds__(256) build_fill_kernel(const int* __restrict__ coords) {
    __shared__ int s_cnt[Kq];
    __shared__ int s_cur[Kq];
    const int tid = threadIdx.x;
    const int v   = blockIdx.x * blockDim.x + tid;
    const bool act = (v < Nq);

    if (tid < Kq) s_cnt[tid] = 0;
    __syncthreads();

    int rn[Kq];
    if (act) {
        int4 cc = __ldg((const int4*)(coords + v * 4));
        int b = cc.x, z = cc.y, y = cc.z, x = cc.w;
        #pragma unroll
        for (int k = 0; k < Kq; k++) {
            int dz = k / 9 - 1, dy = (k / 3) % 3 - 1, dx = k % 3 - 1;
            int nz = z + dz, ny = y + dy, nx = x + dx;
            int r = -1;
            if (nz >= 0 && nz < Dq && ny >= 0 && ny < Hq && nx >= 0 && nx < Wq)
                r = g_table[((b * Dq + nz) * Hq + ny) * Wq + nx];
            rn[k] = r;
            g_nbr[k * Nq + v] = r;
            if (k != 13 && r >= 0) atomicAdd(&s_cnt[k], 1);
        }
    }
    __syncthreads();
    if (tid < Kq && tid != 13)
        s_cur[tid] = atomicAdd(&g_kpos[tid], s_cnt[tid]);
    __syncthreads();
    if (act) {
        int j = 0;
        #pragma unroll
        for (int k = 0; k < Kq; k++) {
            if (rn[k] >= 0) {
                int p;
                if (k == 13) {
                    p = KB13 + v;            // deterministic center slot
                    g_pin[p] = v;
                } else {
                    p = atomicAdd(&s_cur[k], 1);
                    g_pin[p] = rn[k];
                }
                g_plist[(size_t)v * Kq + j] = p;
                j++;
            }
        }
        g_deg[v] = j;
    }
}

// build chunk work-list from final cursors
__global__ void kscan_kernel() {
    __shared__ int s_cb[Kq + 1];
    __shared__ int s_cnt[Kq];
    if (threadIdx.x == 0) {
        int cb = 0;
        for (int k = 0; k < Kq; k++) {
            int cnt = (k == 13) ? Nq : (g_kpos[k] - kbase(k));
            s_cnt[k] = cnt;
            g_kend[k] = kbase(k) + cnt;
            s_cb[k] = cb;
            cb += (cnt + 127) >> 7;
        }
        s_cb[Kq] = cb;
        g_nT = cb;
    }
    __syncthreads();
    for (int k = 0; k < Kq; k++) {
        int nc = s_cb[k + 1] - s_cb[k];
        for (int j = threadIdx.x; j < nc; j += blockDim.x) {
            g_chunk_k[s_cb[k] + j] = k;
            g_chunk_s[s_cb[k] + j] = kbase(k) + 128 * j;
        }
    }
}

// ---------------------------------------------------------------------------
// weight prep: w[k][cin][cout] fp32 -> mma B fragments, single fp16
// ---------------------------------------------------------------------------
__global__ void prep_w_kernel(const float* __restrict__ w, uint2* __restrict__ frag) {
    int idx = blockIdx.x * blockDim.x + threadIdx.x;
    if (idx >= Kq * 1024) return;
    int lane = idx & 31;
    int n8   = (idx >> 5) & 7;
    int kc   = (idx >> 8) & 3;
    int k    = idx >> 10;
    int n  = n8 * 8 + (lane >> 2);
    int c0 = kc * 16 + (lane & 3) * 2;
    uint32_t r[2];
    #pragma unroll
    for (int h = 0; h < 2; h++) {
        uint32_t packed = 0;
        #pragma unroll
        for (int e = 0; e < 2; e++) {
            float x = w[(k * 64 + (c0 + h * 8 + e)) * 64 + n];
            __half hv = __float2half_rn(x);
            uint16_t bits = *(uint16_t*)&hv;
            packed |= (uint32_t)bits << (16 * e);
        }
        r[h] = packed;
    }
    frag[idx] = make_uint2(r[0], r[1]);
}

// ---------------------------------------------------------------------------
// layer 1 (cin=1): direct sparse FMA; 2 threads per voxel
// ---------------------------------------------------------------------------
__global__ void __launch_bounds__(256) layer1_kernel(
    const float* __restrict__ feats, const float* __restrict__ w,
    const float* __restrict__ bias,
    const float* __restrict__ gg, const float* __restrict__ be,
    const float* __restrict__ mm, const float* __restrict__ vv,
    __half* __restrict__ oa)
{
    __shared__ float s_w[Kq * Cq];
    __shared__ float s_scale[Cq], s_shift[Cq];
    const int tid = threadIdx.x;
    if (tid < Cq) {
        float sc = gg[tid] * rsqrtf(vv[tid] + EPSq);
        s_scale[tid] = sc;
        s_shift[tid] = (bias[tid] - mm[tid]) * sc + be[tid];
    }
    for (int t = tid; t < Kq * Cq; t += 256) s_w[t] = w[t];
    __syncthreads();

    int idx = blockIdx.x * blockDim.x + tid;
    int v = idx >> 1;
    if (v >= Nq) return;
    int c0 = (idx & 1) * 32;

    float acc[32];
    #pragma unroll
    for (int c = 0; c < 32; c++) acc[c] = 0.f;

    #pragma unroll
    for (int k = 0; k < Kq; k++) {
        int n = g_nbr[k * Nq + v];
        if (n >= 0) {
            float f = __ldg(&feats[n]);
            const float* wr = &s_w[k * Cq + c0];
            #pragma unroll
            for (int c = 0; c < 32; c++) acc[c] = fmaf(f, wr[c], acc[c]);
        }
    }
    __half2 outp[16];
    #pragma unroll
    for (int c = 0; c < 32; c += 2) {
        float o0 = fmaxf(fmaf(acc[c],     s_scale[c0 + c],     s_shift[c0 + c]),     0.f);
        float o1 = fmaxf(fmaf(acc[c + 1], s_scale[c0 + c + 1], s_shift[c0 + c + 1]), 0.f);
        outp[c >> 1] = __floats2half2_rn(o0, o1);
    }
    uint4* dst = (uint4*)(oa + (size_t)v * Cq + c0);
    const uint4* srcp = (const uint4*)outp;
    dst[0] = srcp[0]; dst[1] = srcp[1]; dst[2] = srcp[2]; dst[3] = srcp[3];
}

// ---------------------------------------------------------------------------
// Phase A: compacted per-offset GEMM, double-buffered persistent CTAs.
// 128 threads (4 warps). smem: A 2x16KB + B 2x8KB = 48KB dynamic.
// ---------------------------------------------------------------------------
#define SMA_A 0
#define SMA_B 32768
#define SMA_TOT 49152

__device__ __forceinline__ void stageA(
    int cidx, int buf, int tid, uint32_t sbase,
    const __half* __restrict__ xa, const uint2* __restrict__ wfrag)
{
    int k    = __ldg(&g_chunk_k[cidx]);
    int p0   = __ldg(&g_chunk_s[cidx]);
    int pend = __ldg(&g_kend[k]);
    // gather A: thread t -> row t
    int p = p0 + tid;
    int n = (p < pend) ? __ldg(&g_pin[p]) : -1;
    const __half* src = xa + (size_t)(n < 0 ? 0 : n) * Cq;
    uint32_t srcsz = (n >= 0) ? 16u : 0u;
    uint32_t dbase = sbase + SMA_A + buf * 16384 + tid * 128;
    uint32_t swz = (tid & 7) << 4;
    #pragma unroll
    for (int j = 0; j < 8; j++)
        cp16(dbase + (((uint32_t)(j << 4)) ^ swz), src + j * 8, srcsz);
    // B fragments: 8KB -> 64B per thread
    const char* wsrc = (const char*)(wfrag + k * 1024) + tid * 64;
    uint32_t wdst = sbase + SMA_B + buf * 8192 + tid * 64;
    #pragma unroll
    for (int j = 0; j < 4; j++)
        cp16(wdst + j * 16, wsrc + j * 16, 16u);
}

__global__ void __launch_bounds__(128) phaseA_kernel(
    const __half* __restrict__ xa, const uint2* __restrict__ wfrag)
{
    extern __shared__ char smc[];
    const uint32_t sbase = smem_u32(smc);
    const int tid  = threadIdx.x;
    const int lane = tid & 31;
    const int warp = tid >> 5;
    const int nT   = g_nT;
    const int step = gridDim.x;

    int c0 = blockIdx.x;
    if (c0 < nT) stageA(c0, 0, tid, sbase, xa, wfrag);
    cp_commit();
    if (c0 + step < nT) stageA(c0 + step, 1, tid, sbase, xa, wfrag);
    cp_commit();

    const int rowl = (lane & 7) | (lane & 8);
    const uint32_t colh = (lane & 16);

    int i = 0;
    for (int c = c0; c < nT; c += step, i++) {
        const int buf = i & 1;
        if (c + step < nT)
            asm volatile("cp.async.wait_group 1;" ::: "memory");
        else
            asm volatile("cp.async.wait_group 0;" ::: "memory");
        __syncthreads();

        int k    = __ldg(&g_chunk_k[c]);
        int p0   = __ldg(&g_chunk_s[c]);
        int pend = __ldg(&g_kend[k]);

        const uint32_t sa = sbase + SMA_A + buf * 16384;
        const uint2* sb = (const uint2*)(smc + SMA_B + buf * 8192);

        float d[2][8][4];
        #pragma unroll
        for (int rt = 0; rt < 2; rt++)
            #pragma unroll
            for (int a = 0; a < 8; a++)
                #pragma unroll
                for (int b = 0; b < 4; b++) d[rt][a][b] = 0.f;

        #pragma unroll
        for (int kc = 0; kc < 4; kc++) {
            int row0 = warp * 32 + rowl;
            uint32_t swz0 = (row0 & 7) << 4;
            uint32_t boff = ((uint32_t)((kc << 5) | colh)) ^ swz0;
            uint32_t a0[4], a1[4];
            ldm_x4(a0, sa + row0 * 128 + boff);
            ldm_x4(a1, sa + (row0 + 16) * 128 + boff);
            #pragma unroll
            for (int n8 = 0; n8 < 8; n8++) {
                uint2 bh = sb[(kc * 8 + n8) * 32 + lane];
                mma_f16(d[0][n8], a0, bh.x, bh.y);
                mma_f16(d[1][n8], a1, bh.x, bh.y);
            }
        }

        // store raw partials (fp16), predicated on segment end
        #pragma unroll
        for (int rt = 0; rt < 2; rt++) {
            int r0 = warp * 32 + rt * 16 + (lane >> 2);
            int r1 = r0 + 8;
            bool v0 = (p0 + r0) < pend;
            bool v1 = (p0 + r1) < pend;
            __half* row0p = (__half*)(g_stg + (size_t)(p0 + r0) * Cq);
            __half* row1p = (__half*)(g_stg + (size_t)(p0 + r1) * Cq);
            #pragma unroll
            for (int n8 = 0; n8 < 8; n8++) {
                int col = n8 * 8 + (lane & 3) * 2;
                if (v0) *(__half2*)(row0p + col) = __floats2half2_rn(d[rt][n8][0], d[rt][n8][1]);
                if (v1) *(__half2*)(row1p + col) = __floats2half2_rn(d[rt][n8][2], d[rt][n8][3]);
            }
        }
        __syncthreads();
        if (c + 2 * step < nT)
            stageA(c + 2 * step, buf, tid, sbase, xa, wfrag);
        cp_commit();
    }
}

// ---------------------------------------------------------------------------
// Phase B: per-voxel segmented reduction (2-row batched) + bias + BN + ReLU
// 4 threads per voxel, 16 channels each.
// ---------------------------------------------------------------------------
__global__ void __launch_bounds__(256) phaseB_kernel(
    const float* __restrict__ bias,
    const float* __restrict__ gg, const float* __restrict__ be,
    const float* __restrict__ mm, const float* __restrict__ vv,
    float* __restrict__ out_f32, __half* __restrict__ oa, int outmode)
{
    __shared__ float s_scale[Cq], s_shift[Cq];
    const int tid = threadIdx.x;
    if (tid < Cq) {
        float sc = gg[tid] * rsqrtf(vv[tid] + EPSq);
        s_scale[tid] = sc;
        s_shift[tid] = (bias[tid] - mm[tid]) * sc + be[tid];
    }
    __syncthreads();

    int v = blockIdx.x * 64 + (tid >> 2);
    if (v >= Nq) return;
    int c0 = (tid & 3) * 16;

    float acc[16];
    #pragma unroll
    for (int c = 0; c < 16; c++) acc[c] = 0.f;

    int deg = g_deg[v];
    const int* pl = &g_plist[(size_t)v * Kq];

    int j = 0;
    for (; j + 2 <= deg; j += 2) {
        int p0 = __ldg(&pl[j]);
        int p1 = __ldg(&pl[j + 1]);
        const uint4* ra = (const uint4*)(g_stg + (size_t)p0 * Cq + c0);
        const uint4* rb = (const uint4*)(g_stg + (size_t)p1 * Cq + c0);
        uint4 qa0 = __ldg(&ra[0]);
        uint4 qa1 = __ldg(&ra[1]);
        uint4 qb0 = __ldg(&rb[0]);
        uint4 qb1 = __ldg(&rb[1]);
        const __half2* ha0 = (const __half2*)&qa0;
        const __half2* ha1 = (const __half2*)&qa1;
        const __half2* hb0 = (const __half2*)&qb0;
        const __half2* hb1 = (const __half2*)&qb1;
        #pragma unroll
        for (int e = 0; e < 4; e++) {
            float2 fa0 = __half22float2(ha0[e]);
            float2 fa1 = __half22float2(ha1[e]);
            float2 fb0 = __half22float2(hb0[e]);
            float2 fb1 = __half22float2(hb1[e]);
            acc[e * 2 + 0]     += fa0.x + fb0.x;
            acc[e * 2 + 1]     += fa0.y + fb0.y;
            acc[8 + e * 2 + 0] += fa1.x + fb1.x;
            acc[8 + e * 2 + 1] += fa1.y + fb1.y;
        }
    }
    for (; j < deg; j++) {
        int p = __ldg(&pl[j]);
        const uint4* row = (const uint4*)(g_stg + (size_t)p * Cq + c0);
        uint4 q0 = __ldg(&row[0]);
        uint4 q1 = __ldg(&row[1]);
        const __half2* h0 = (const __half2*)&q0;
        const __half2* h1 = (const __half2*)&q1;
        #pragma unroll
        for (int e = 0; e < 4; e++) {
            float2 f0 = __half22float2(h0[e]);
            float2 f1 = __half22float2(h1[e]);
            acc[e * 2 + 0]     += f0.x;
            acc[e * 2 + 1]     += f0.y;
            acc[8 + e * 2 + 0] += f1.x;
            acc[8 + e * 2 + 1] += f1.y;
        }
    }

    if (outmode == 0) {
        float4 o[4];
        #pragma unroll
        for (int e = 0; e < 4; e++) {
            float* oe = (float*)&o[e];
            #pragma unroll
            for (int u = 0; u < 4; u++) {
                int c = e * 4 + u;
                oe[u] = fmaxf(fmaf(acc[c], s_scale[c0 + c], s_shift[c0 + c]), 0.f);
            }
        }
        float4* dst = (float4*)(out_f32 + (size_t)v * Cq + c0);
        dst[0] = o[0]; dst[1] = o[1]; dst[2] = o[2]; dst[3] = o[3];
    } else {
        __half2 hp[8];
        #pragma unroll
        for (int e = 0; e < 8; e++) {
            int c = e * 2;
            float o0 = fmaxf(fmaf(acc[c],     s_scale[c0 + c],     s_shift[c0 + c]),     0.f);
            float o1 = fmaxf(fmaf(acc[c + 1], s_scale[c0 + c + 1], s_shift[c0 + c + 1]), 0.f);
            hp[e] = __floats2half2_rn(o0, o1);
        }
        uint4* dst = (uint4*)(oa + (size_t)v * Cq + c0);
        const uint4* srcp = (const uint4*)hp;
        dst[0] = srcp[0]; dst[1] = srcp[1];
    }
}

// ---------------------------------------------------------------------------
extern "C" void kernel_launch(void* const* d_in, const int* in_sizes, int n_in,
                              void* d_out, int out_size)
{
    const float* feats  = (const float*)d_in[0];
    const int*   coords = (const int*)  d_in[1];
    const float* w1 = (const float*)d_in[2];
    const float* b1 = (const float*)d_in[3];
    const float* g1 = (const float*)d_in[4];
    const float* be1= (const float*)d_in[5];
    const float* m1 = (const float*)d_in[6];
    const float* v1 = (const float*)d_in[7];
    const float* w2 = (const float*)d_in[8];
    const float* b2 = (const float*)d_in[9];
    const float* g2 = (const float*)d_in[10];
    const float* be2= (const float*)d_in[11];
    const float* m2 = (const float*)d_in[12];
    const float* v2 = (const float*)d_in[13];
    const float* w3 = (const float*)d_in[14];
    const float* b3 = (const float*)d_in[15];
    const float* g3 = (const float*)d_in[16];
    const float* be3= (const float*)d_in[17];
    const float* m3 = (const float*)d_in[18];
    const float* v3 = (const float*)d_in[19];
    float* out = (float*)d_out;

    cudaFuncSetAttribute(phaseA_kernel,
                         cudaFuncAttributeMaxDynamicSharedMemorySize, SMA_TOT);

    uint2 *wf2, *wf3;
    cudaGetSymbolAddress((void**)&wf2, g_wf2);
    cudaGetSymbolAddress((void**)&wf3, g_wf3);
    __half *a1, *a2;
    cudaGetSymbolAddress((void**)&a1, g_a1);
    cudaGetSymbolAddress((void**)&a2, g_a2);

    // rulebook (one-pass fill) + weight prep
    init_table_kernel<<<4096, 256>>>();
    scatter_kernel<<<(Nq + 255) / 256, 256>>>(coords);
    prep_w_kernel<<<(Kq * 1024 + 255) / 256, 256>>>(w2, wf2);
    prep_w_kernel<<<(Kq * 1024 + 255) / 256, 256>>>(w3, wf3);
    build_fill_kernel<<<(Nq + 255) / 256, 256>>>(coords);
    kscan_kernel<<<1, 256>>>();

    // layer 1
    layer1_kernel<<<(Nq * 2 + 255) / 256, 256>>>(feats, w1, b1, g1, be1, m1, v1, a1);
    // layer 2
    phaseA_kernel<<<PA_GRID, 128, SMA_TOT>>>(a1, wf2);
    phaseB_kernel<<<(Nq + 63) / 64, 256>>>(b2, g2, be2, m2, v2, nullptr, a2, 1);
    // layer 3
    phaseA_kernel<<<PA_GRID, 128, SMA_TOT>>>(a2, wf3);
    phaseB_kernel<<<(Nq + 63) / 64, 256>>>(b3, g3, be3, m3, v3, out, nullptr, 0);
}

// round 10
// speedup vs baseline: 1.6754x; 1.0878x over previous
#include <cuda_runtime.h>
#include <cuda_fp16.h>
#include <cstdint>

#define Nq 400000
#define Kq 27
#define Cq 64
#define Dq 128
#define Hq 128
#define Wq 128
#define EPSq 1e-5f
#define TABLE_SIZE (2 * Dq * Hq * Wq)   // 4,194,304
#define SEGK 49152                       // per-offset staging capacity (k != 13)
#define KB13 (13 * SEGK)                 // center segment base; size Nq exactly
#define CAPq (KB13 + Nq + 13 * SEGK)     // 1,677,952 pair rows
#define MAXCHUNK 8192
#define PA_GRID 296

// ---- scratch (device globals; allocation-free rule) ----
__device__ int   g_table[TABLE_SIZE];
__device__ int   g_kpos[32];              // per-offset fill cursors
__device__ int   g_kend[32];              // segment end (base + count)
__device__ int   g_nT;                    // total 256-row chunks
__device__ int   g_chunk_k[MAXCHUNK];
__device__ int   g_chunk_s[MAXCHUNK];     // start pair index of chunk
__device__ int   g_pin[CAPq];             // pair -> input voxel
__device__ int   g_plist[(size_t)Nq * Kq];// voxel-major pair ids
__device__ int   g_deg[Nq];
__device__ __half g_stg[(size_t)CAPq * Cq];  // staged partials (permuted layout)
__device__ __half g_a1[(size_t)Nq * Cq];
__device__ __half g_a2[(size_t)Nq * Cq];
__device__ uint2 g_wf2[Kq * 1024];        // B fragments fp16
__device__ uint2 g_wf3[Kq * 1024];

__host__ __device__ __forceinline__ int kbase(int k) {
    return (k <= 13) ? k * SEGK : KB13 + Nq + (k - 14) * SEGK;
}
__device__ __forceinline__ int kdecode(int p) {
    if (p >= KB13)
        return (p < KB13 + Nq) ? 13 : 14 + (p - (KB13 + Nq)) / SEGK;
    return p / SEGK;
}

// ---------------------------------------------------------------------------
// helpers
// ---------------------------------------------------------------------------
__device__ __forceinline__ uint32_t smem_u32(const void* p) {
    uint32_t a;
    asm("{ .reg .u64 t; cvta.to.shared.u64 t, %1; cvt.u32.u64 %0, t; }" : "=r"(a) : "l"(p));
    return a;
}
__device__ __forceinline__ void mma_f16(float* d, const uint32_t* a, uint32_t b0, uint32_t b1) {
    asm volatile(
        "mma.sync.aligned.m16n8k16.row.col.f32.f16.f16.f32 "
        "{%0,%1,%2,%3}, {%4,%5,%6,%7}, {%8,%9}, {%0,%1,%2,%3};"
        : "+f"(d[0]), "+f"(d[1]), "+f"(d[2]), "+f"(d[3])
        : "r"(a[0]), "r"(a[1]), "r"(a[2]), "r"(a[3]), "r"(b0), "r"(b1));
}
__device__ __forceinline__ void ldm_x4(uint32_t* a, uint32_t addr) {
    asm volatile(
        "ldmatrix.sync.aligned.m8n8.x4.shared.b16 {%0,%1,%2,%3}, [%4];"
        : "=r"(a[0]), "=r"(a[1]), "=r"(a[2]), "=r"(a[3]) : "r"(addr));
}
__device__ __forceinline__ void cp16(uint32_t dst, const void* src, uint32_t srcsize) {
    asm volatile("cp.async.cg.shared.global [%0], [%1], 16, %2;"
                 :: "r"(dst), "l"(src), "r"(srcsize) : "memory");
}
__device__ __forceinline__ void cp_commit() {
    asm volatile("cp.async.commit_group;" ::: "memory");
}

// ---------------------------------------------------------------------------
// rulebook
// ---------------------------------------------------------------------------
__global__ void init_table_kernel() {
    int i = blockIdx.x * blockDim.x + threadIdx.x;
    ((int4*)g_table)[i] = make_int4(-1, -1, -1, -1);
    if (blockIdx.x == 0 && threadIdx.x < Kq) g_kpos[threadIdx.x] = kbase(threadIdx.x);
}

__global__ void scatter_kernel(const int* __restrict__ coords) {
    int i = blockIdx.x * blockDim.x + threadIdx.x;
    if (i >= Nq) return;
    int b = coords[i * 4 + 0], z = coords[i * 4 + 1];
    int y = coords[i * 4 + 2], x = coords[i * 4 + 3];
    g_table[((b * Dq + z) * Hq + y) * Wq + x] = i;
}

// one pass: neighbor lookups + pair fill (fixed per-k segments)
__global__ void __launch_bounds__(256) build_fill_kernel(const int* __restrict__ coords) {
    __shared__ int s_cnt[Kq];
    __shared__ int s_cur[Kq];
    const int tid = threadIdx.x;
    const int v   = blockIdx.x * blockDim.x + tid;
    const bool act = (v < Nq);

    if (tid < Kq) s_cnt[tid] = 0;
    __syncthreads();

    int rn[Kq];
    if (act) {
        int4 cc = __ldg((const int4*)(coords + v * 4));
        int b = cc.x, z = cc.y, y = cc.z, x = cc.w;
        #pragma unroll
        for (int k = 0; k < Kq; k++) {
            int dz = k / 9 - 1, dy = (k / 3) % 3 - 1, dx = k % 3 - 1;
            int nz = z + dz, ny = y + dy, nx = x + dx;
            int r = -1;
            if (nz >= 0 && nz < Dq && ny >= 0 && ny < Hq && nx >= 0 && nx < Wq)
                r = g_table[((b * Dq + nz) * Hq + ny) * Wq + nx];
            rn[k] = r;
            if (k != 13 && r >= 0) atomicAdd(&s_cnt[k], 1);
        }
    }
    __syncthreads();
    if (tid < Kq && tid != 13)
        s_cur[tid] = atomicAdd(&g_kpos[tid], s_cnt[tid]);
    __syncthreads();
    if (act) {
        int j = 0;
        #pragma unroll
        for (int k = 0; k < Kq; k++) {
            if (rn[k] >= 0) {
                int p;
                if (k == 13) {
                    p = KB13 + v;            // deterministic center slot
                    g_pin[p] = v;
                } else {
                    p = atomicAdd(&s_cur[k], 1);
                    g_pin[p] = rn[k];
                }
                g_plist[(size_t)v * Kq + j] = p;
                j++;
            }
        }
        g_deg[v] = j;
    }
}

// build 256-row chunk work-list from final cursors
__global__ void kscan_kernel() {
    __shared__ int s_cb[Kq + 1];
    if (threadIdx.x == 0) {
        int cb = 0;
        for (int k = 0; k < Kq; k++) {
            int cnt = (k == 13) ? Nq : (g_kpos[k] - kbase(k));
            g_kend[k] = kbase(k) + cnt;
            s_cb[k] = cb;
            cb += (cnt + 255) >> 8;
        }
        s_cb[Kq] = cb;
        g_nT = cb;
    }
    __syncthreads();
    for (int k = 0; k < Kq; k++) {
        int nc = s_cb[k + 1] - s_cb[k];
        for (int j = threadIdx.x; j < nc; j += blockDim.x) {
            g_chunk_k[s_cb[k] + j] = k;
            g_chunk_s[s_cb[k] + j] = kbase(k) + 256 * j;
        }
    }
}

// ---------------------------------------------------------------------------
// weight prep: w[k][cin][cout] fp32 -> mma B fragments, single fp16
// ---------------------------------------------------------------------------
__global__ void prep_w_kernel(const float* __restrict__ w, uint2* __restrict__ frag) {
    int idx = blockIdx.x * blockDim.x + threadIdx.x;
    if (idx >= Kq * 1024) return;
    int lane = idx & 31;
    int n8   = (idx >> 5) & 7;
    int kc   = (idx >> 8) & 3;
    int k    = idx >> 10;
    int n  = n8 * 8 + (lane >> 2);
    int c0 = kc * 16 + (lane & 3) * 2;
    uint32_t r[2];
    #pragma unroll
    for (int h = 0; h < 2; h++) {
        uint32_t packed = 0;
        #pragma unroll
        for (int e = 0; e < 2; e++) {
            float x = w[(k * 64 + (c0 + h * 8 + e)) * 64 + n];
            __half hv = __float2half_rn(x);
            uint16_t bits = *(uint16_t*)&hv;
            packed |= (uint32_t)bits << (16 * e);
        }
        r[h] = packed;
    }
    frag[idx] = make_uint2(r[0], r[1]);
}

// ---------------------------------------------------------------------------
// layer 1 (cin=1): pair-list walk; 2 threads per voxel (32 channels each)
// ---------------------------------------------------------------------------
__global__ void __launch_bounds__(256) layer1_kernel(
    const float* __restrict__ feats, const float* __restrict__ w,
    const float* __restrict__ bias,
    const float* __restrict__ gg, const float* __restrict__ be,
    const float* __restrict__ mm, const float* __restrict__ vv,
    __half* __restrict__ oa)
{
    __shared__ float s_w[Kq * Cq];
    __shared__ float s_scale[Cq], s_shift[Cq];
    const int tid = threadIdx.x;
    if (tid < Cq) {
        float sc = gg[tid] * rsqrtf(vv[tid] + EPSq);
        s_scale[tid] = sc;
        s_shift[tid] = (bias[tid] - mm[tid]) * sc + be[tid];
    }
    for (int t = tid; t < Kq * Cq; t += 256) s_w[t] = w[t];
    __syncthreads();

    int idx = blockIdx.x * blockDim.x + tid;
    int v = idx >> 1;
    if (v >= Nq) return;
    int c0 = (idx & 1) * 32;

    float acc[32];
    #pragma unroll
    for (int c = 0; c < 32; c++) acc[c] = 0.f;

    int deg = g_deg[v];
    const int* pl = &g_plist[(size_t)v * Kq];
    for (int j = 0; j < deg; j++) {
        int p = __ldg(&pl[j]);
        int k = kdecode(p);
        int n = __ldg(&g_pin[p]);
        float f = __ldg(&feats[n]);
        const float* wr = &s_w[k * Cq + c0];
        #pragma unroll
        for (int c = 0; c < 32; c++) acc[c] = fmaf(f, wr[c], acc[c]);
    }
    __half2 outp[16];
    #pragma unroll
    for (int c = 0; c < 32; c += 2) {
        float o0 = fmaxf(fmaf(acc[c],     s_scale[c0 + c],     s_shift[c0 + c]),     0.f);
        float o1 = fmaxf(fmaf(acc[c + 1], s_scale[c0 + c + 1], s_shift[c0 + c + 1]), 0.f);
        outp[c >> 1] = __floats2half2_rn(o0, o1);
    }
    uint4* dst = (uint4*)(oa + (size_t)v * Cq + c0);
    const uint4* srcp = (const uint4*)outp;
    dst[0] = srcp[0]; dst[1] = srcp[1]; dst[2] = srcp[2]; dst[3] = srcp[3];
}

// ---------------------------------------------------------------------------
// Phase A: compacted per-offset GEMM, 256-row chunks, double-buffered,
// persistent CTAs, permuted staging layout ([q:4][n8:8][e:2] per 128B row).
// 256 threads (8 warps x 32 rows). smem: A 2x32KB + B 2x8KB = 80KB.
// ---------------------------------------------------------------------------
#define SMA_A 0
#define SMA_B 65536
#define SMA_TOT 81920

__device__ __forceinline__ void stageA(
    int cidx, int buf, int tid, uint32_t sbase,
    const __half* __restrict__ xa, const uint2* __restrict__ wfrag)
{
    int k    = __ldg(&g_chunk_k[cidx]);
    int p0   = __ldg(&g_chunk_s[cidx]);
    int pend = __ldg(&g_kend[k]);
    int p = p0 + tid;
    int n = (p < pend) ? __ldg(&g_pin[p]) : -1;
    const __half* src = xa + (size_t)(n < 0 ? 0 : n) * Cq;
    uint32_t srcsz = (n >= 0) ? 16u : 0u;
    uint32_t dbase = sbase + SMA_A + buf * 32768 + tid * 128;
    uint32_t swz = (tid & 7) << 4;
    #pragma unroll
    for (int j = 0; j < 8; j++)
        cp16(dbase + (((uint32_t)(j << 4)) ^ swz), src + j * 8, srcsz);
    const char* wsrc = (const char*)(wfrag + k * 1024) + tid * 32;
    uint32_t wdst = sbase + SMA_B + buf * 8192 + tid * 32;
    cp16(wdst,      wsrc,      16u);
    cp16(wdst + 16, wsrc + 16, 16u);
}

__global__ void __launch_bounds__(256) phaseA_kernel(
    const __half* __restrict__ xa, const uint2* __restrict__ wfrag)
{
    extern __shared__ char smc[];
    const uint32_t sbase = smem_u32(smc);
    const int tid  = threadIdx.x;
    const int lane = tid & 31;
    const int warp = tid >> 5;
    const int nT   = g_nT;
    const int step = gridDim.x;

    int c0 = blockIdx.x;
    if (c0 < nT) stageA(c0, 0, tid, sbase, xa, wfrag);
    cp_commit();
    if (c0 + step < nT) stageA(c0 + step, 1, tid, sbase, xa, wfrag);
    cp_commit();

    const int rowl = (lane & 7) | (lane & 8);
    const uint32_t colh = (lane & 16);
    const int qrow = lane >> 2;
    const int qq   = lane & 3;

    int i = 0;
    for (int c = c0; c < nT; c += step, i++) {
        const int buf = i & 1;
        if (c + step < nT)
            asm volatile("cp.async.wait_group 1;" ::: "memory");
        else
            asm volatile("cp.async.wait_group 0;" ::: "memory");
        __syncthreads();

        int k    = __ldg(&g_chunk_k[c]);
        int p0   = __ldg(&g_chunk_s[c]);
        int pend = __ldg(&g_kend[k]);

        const uint32_t sa = sbase + SMA_A + buf * 32768;
        const uint2* sb = (const uint2*)(smc + SMA_B + buf * 8192);

        float d[2][8][4];
        #pragma unroll
        for (int rt = 0; rt < 2; rt++)
            #pragma unroll
            for (int a = 0; a < 8; a++)
                #pragma unroll
                for (int b = 0; b < 4; b++) d[rt][a][b] = 0.f;

        #pragma unroll
        for (int kc = 0; kc < 4; kc++) {
            int row0 = warp * 32 + rowl;
            uint32_t swz0 = (row0 & 7) << 4;
            uint32_t boff = ((uint32_t)((kc << 5) | colh)) ^ swz0;
            uint32_t a0[4], a1[4];
            ldm_x4(a0, sa + row0 * 128 + boff);
            ldm_x4(a1, sa + (row0 + 16) * 128 + boff);
            #pragma unroll
            for (int n8 = 0; n8 < 8; n8++) {
                uint2 bh = sb[(kc * 8 + n8) * 32 + lane];
                mma_f16(d[0][n8], a0, bh.x, bh.y);
                mma_f16(d[1][n8], a1, bh.x, bh.y);
            }
        }

        // permuted-layout staging stores: 2x STG.128 per row
        #pragma unroll
        for (int rt = 0; rt < 2; rt++) {
            int r0 = warp * 32 + rt * 16 + qrow;
            int r1 = r0 + 8;
            __half2 h0[8], h1[8];
            #pragma unroll
            for (int n8 = 0; n8 < 8; n8++) {
                h0[n8] = __floats2half2_rn(d[rt][n8][0], d[rt][n8][1]);
                h1[n8] = __floats2half2_rn(d[rt][n8][2], d[rt][n8][3]);
            }
            if (p0 + r0 < pend) {
                uint4* dst = (uint4*)((char*)g_stg + (size_t)(p0 + r0) * 128 + qq * 32);
                dst[0] = ((const uint4*)h0)[0];
                dst[1] = ((const uint4*)h0)[1];
            }
            if (p0 + r1 < pend) {
                uint4* dst = (uint4*)((char*)g_stg + (size_t)(p0 + r1) * 128 + qq * 32);
                dst[0] = ((const uint4*)h1)[0];
                dst[1] = ((const uint4*)h1)[1];
            }
        }
        __syncthreads();
        if (c + 2 * step < nT)
            stageA(c + 2 * step, buf, tid, sbase, xa, wfrag);
        cp_commit();
    }
}

// ---------------------------------------------------------------------------
// Phase B: per-voxel segmented reduction (permuted layout) + bias + BN + ReLU
// 4 threads per voxel; thread sub handles channels {n8*8 + sub*2 + e}.
// ---------------------------------------------------------------------------
__global__ void __launch_bounds__(256) phaseB_kernel(
    const float* __restrict__ bias,
    const float* __restrict__ gg, const float* __restrict__ be,
    const float* __restrict__ mm, const float* __restrict__ vv,
    float* __restrict__ out_f32, __half* __restrict__ oa, int outmode)
{
    __shared__ float s_scale[Cq], s_shift[Cq];
    const int tid = threadIdx.x;
    if (tid < Cq) {
        float sc = gg[tid] * rsqrtf(vv[tid] + EPSq);
        s_scale[tid] = sc;
        s_shift[tid] = (bias[tid] - mm[tid]) * sc + be[tid];
    }
    __syncthreads();

    int v = blockIdx.x * 64 + (tid >> 2);
    if (v >= Nq) return;
    int sub = tid & 3;

    float acc[16];
    #pragma unroll
    for (int c = 0; c < 16; c++) acc[c] = 0.f;

    int deg = g_deg[v];
    const int* pl = &g_plist[(size_t)v * Kq];

    int j = 0;
    for (; j + 2 <= deg; j += 2) {
        int p0 = __ldg(&pl[j]);
        int p1 = __ldg(&pl[j + 1]);
        const uint4* ra = (const uint4*)((const char*)g_stg + (size_t)p0 * 128 + sub * 32);
        const uint4* rb = (const uint4*)((const char*)g_stg + (size_t)p1 * 128 + sub * 32);
        uint4 qa0 = __ldg(&ra[0]);
        uint4 qa1 = __ldg(&ra[1]);
        uint4 qb0 = __ldg(&rb[0]);
        uint4 qb1 = __ldg(&rb[1]);
        const __half2* ha0 = (const __half2*)&qa0;
        const __half2* ha1 = (const __half2*)&qa1;
        const __half2* hb0 = (const __half2*)&qb0;
        const __half2* hb1 = (const __half2*)&qb1;
        #pragma unroll
        for (int e = 0; e < 4; e++) {
            float2 fa0 = __half22float2(ha0[e]);
            float2 fa1 = __half22float2(ha1[e]);
            float2 fb0 = __half22float2(hb0[e]);
            float2 fb1 = __half22float2(hb1[e]);
            acc[e * 2 + 0]     += fa0.x + fb0.x;
            acc[e * 2 + 1]     += fa0.y + fb0.y;
            acc[8 + e * 2 + 0] += fa1.x + fb1.x;
            acc[8 + e * 2 + 1] += fa1.y + fb1.y;
        }
    }
    for (; j < deg; j++) {
        int p = __ldg(&pl[j]);
        const uint4* row = (const uint4*)((const char*)g_stg + (size_t)p * 128 + sub * 32);
        uint4 q0 = __ldg(&row[0]);
        uint4 q1 = __ldg(&row[1]);
        const __half2* h0 = (const __half2*)&q0;
        const __half2* h1 = (const __half2*)&q1;
        #pragma unroll
        for (int e = 0; e < 4; e++) {
            float2 f0 = __half22float2(h0[e]);
            float2 f1 = __half22float2(h1[e]);
            acc[e * 2 + 0]     += f0.x;
            acc[e * 2 + 1]     += f0.y;
            acc[8 + e * 2 + 0] += f1.x;
            acc[8 + e * 2 + 1] += f1.y;
        }
    }

    // acc[h] corresponds to channel c = (h>>1)*8 + sub*2 + (h&1)
    if (outmode == 0) {
        float* orow = out_f32 + (size_t)v * Cq;
        #pragma unroll
        for (int n8 = 0; n8 < 8; n8++) {
            int c = n8 * 8 + sub * 2;
            float o0 = fmaxf(fmaf(acc[n8 * 2 + 0], s_scale[c],     s_shift[c]),     0.f);
            float o1 = fmaxf(fmaf(acc[n8 * 2 + 1], s_scale[c + 1], s_shift[c + 1]), 0.f);
            *(float2*)(orow + c) = make_float2(o0, o1);
        }
    } else {
        __half* orow = oa + (size_t)v * Cq;
        #pragma unroll
        for (int n8 = 0; n8 < 8; n8++) {
            int c = n8 * 8 + sub * 2;
            float o0 = fmaxf(fmaf(acc[n8 * 2 + 0], s_scale[c],     s_shift[c]),     0.f);
            float o1 = fmaxf(fmaf(acc[n8 * 2 + 1], s_scale[c + 1], s_shift[c + 1]), 0.f);
            *(__half2*)(orow + c) = __floats2half2_rn(o0, o1);
        }
    }
}

// ---------------------------------------------------------------------------
extern "C" void kernel_launch(void* const* d_in, const int* in_sizes, int n_in,
                              void* d_out, int out_size)
{
    const float* feats  = (const float*)d_in[0];
    const int*   coords = (const int*)  d_in[1];
    const float* w1 = (const float*)d_in[2];
    const float* b1 = (const float*)d_in[3];
    const float* g1 = (const float*)d_in[4];
    const float* be1= (const float*)d_in[5];
    const float* m1 = (const float*)d_in[6];
    const float* v1 = (const float*)d_in[7];
    const float* w2 = (const float*)d_in[8];
    const float* b2 = (const float*)d_in[9];
    const float* g2 = (const float*)d_in[10];
    const float* be2= (const float*)d_in[11];
    const float* m2 = (const float*)d_in[12];
    const float* v2 = (const float*)d_in[13];
    const float* w3 = (const float*)d_in[14];
    const float* b3 = (const float*)d_in[15];
    const float* g3 = (const float*)d_in[16];
    const float* be3= (const float*)d_in[17];
    const float* m3 = (const float*)d_in[18];
    const float* v3 = (const float*)d_in[19];
    float* out = (float*)d_out;

    cudaFuncSetAttribute(phaseA_kernel,
                         cudaFuncAttributeMaxDynamicSharedMemorySize, SMA_TOT);

    uint2 *wf2, *wf3;
    cudaGetSymbolAddress((void**)&wf2, g_wf2);
    cudaGetSymbolAddress((void**)&wf3, g_wf3);
    __half *a1, *a2;
    cudaGetSymbolAddress((void**)&a1, g_a1);
    cudaGetSymbolAddress((void**)&a2, g_a2);

    // rulebook (one-pass fill) + weight prep
    init_table_kernel<<<4096, 256>>>();
    scatter_kernel<<<(Nq + 255) / 256, 256>>>(coords);
    prep_w_kernel<<<(Kq * 1024 + 255) / 256, 256>>>(w2, wf2);
    prep_w_kernel<<<(Kq * 1024 + 255) / 256, 256>>>(w3, wf3);
    build_fill_kernel<<<(Nq + 255) / 256, 256>>>(coords);
    kscan_kernel<<<1, 256>>>();

    // layer 1
    layer1_kernel<<<(Nq * 2 + 255) / 256, 256>>>(feats, w1, b1, g1, be1, m1, v1, a1);
    // layer 2
    phaseA_kernel<<<PA_GRID, 256, SMA_TOT>>>(a1, wf2);
    phaseB_kernel<<<(Nq + 63) / 64, 256>>>(b2, g2, be2, m2, v2, nullptr, a2, 1);
    // layer 3
    phaseA_kernel<<<PA_GRID, 256, SMA_TOT>>>(a2, wf3);
    phaseB_kernel<<<(Nq + 63) / 64, 256>>>(b3, g3, be3, m3, v3, out, nullptr, 0);
}